// round 1
// baseline (speedup 1.0000x reference)
#include <cuda_runtime.h>

#define H 64
#define NB_MAX 66          // max intervals (<= 65) + slack
#define E_MAX 50048
#define N_MAX 20032

// ---------------- scratch (static device globals; no allocation) ----------------
__device__ __align__(16) float g_P[NB_MAX * H * H];   // per-bucket P tables [k][i*64+o]
__device__ __align__(16) float g_Q[NB_MAX * H * H];   // per-bucket Q tables
__device__ float g_bounds[NB_MAX + 2];
__device__ int   g_m;        // number of interior thresholds in (0,1); intervals = m+1
__device__ int   g_is64;     // edge_index dtype autodetect
__device__ int   g_src[E_MAX], g_dst[E_MAX], g_bucket[E_MAX], g_order[E_MAX];
__device__ float g_a[E_MAX];
__device__ int   g_hist[NB_MAX + 2], g_off[NB_MAX + 2], g_cursor[NB_MAX + 2];
__device__ __align__(16) float g_agg[N_MAX * H];      // NNConv output pre-BN
__device__ __align__(16) float g_rwT[H * H];          // root_w transposed [i][o]
__device__ float g_sum[H], g_sq[H];

// ---------------- k1: thresholds, sort, dtype detect, hist zero ----------------
__global__ void k1_setup(const float* __restrict__ w1, const float* __restrict__ b1,
                         const void* __restrict__ eidx, int E, int N) {
    __shared__ float cand[H];
    __shared__ int   valid[H];
    __shared__ int   bad;
    int t = threadIdx.x;   // 64 threads
    if (t == 0) bad = 0;
    float w = w1[t], b = b1[t];
    float th = 0.f; int v = 0;
    if (w != 0.f) {
        th = -b / w;
        if (th > 0.f && th < 1.f) v = 1;
    }
    cand[t] = th; valid[t] = v;
    __syncthreads();
    // int64-vs-int32 autodetect: interpret buffer as int64; int32 data shows huge values
    const long long* p64 = (const long long*)eidx;
    for (int s = t; s < 512; s += 64) {
        long long vl = p64[s];
        if (vl < 0 || vl >= (long long)N) bad = 1;
    }
    __syncthreads();
    if (t == 0) {
        g_is64 = (bad == 0) ? 1 : 0;
        float arr[H];
        int m = 0;
        for (int j = 0; j < H; j++) if (valid[j]) arr[m++] = cand[j];
        for (int i = 1; i < m; i++) {          // insertion sort (tiny)
            float xv = arr[i]; int j = i - 1;
            while (j >= 0 && arr[j] > xv) { arr[j + 1] = arr[j]; j--; }
            arr[j + 1] = xv;
        }
        g_bounds[0] = 0.f;
        for (int i = 0; i < m; i++) g_bounds[i + 1] = arr[i];
        g_bounds[m + 1] = 1.0f;
        g_m = m;
    }
    for (int i = t; i < NB_MAX + 2; i += 64) g_hist[i] = 0;
}

// ---------------- k2: build P_k / Q_k tables ----------------
__global__ void k2_tables(const float* __restrict__ w1, const float* __restrict__ b1,
                          const float* __restrict__ w2, const float* __restrict__ b2) {
    int k = blockIdx.x;
    if (k > g_m) return;
    __shared__ float wm[H], bm[H];
    int t = threadIdx.x;   // 256
    if (t < H) {
        float amid = 0.5f * (g_bounds[k] + g_bounds[k + 1]);
        float w = w1[t], b = b1[t];
        bool act = (amid * w + b) > 0.f;
        wm[t] = act ? w : 0.f;
        bm[t] = act ? b : 0.f;
    }
    __syncthreads();
    const float4* w2v = (const float4*)w2;
    for (int f = t; f < H * H; f += 256) {
        float p = 0.f, q = 0.f;
#pragma unroll
        for (int j4 = 0; j4 < 16; j4++) {
            float4 wv = w2v[f * 16 + j4];
            p += wm[j4*4+0]*wv.x + wm[j4*4+1]*wv.y + wm[j4*4+2]*wv.z + wm[j4*4+3]*wv.w;
            q += bm[j4*4+0]*wv.x + bm[j4*4+1]*wv.y + bm[j4*4+2]*wv.z + bm[j4*4+3]*wv.w;
        }
        g_P[k * H * H + f] = p;
        g_Q[k * H * H + f] = q + b2[f];
    }
}

// ---------------- k3: per-edge bucket + histogram + decode indices ----------------
__global__ void k3_prep(const float* __restrict__ eattr, const void* __restrict__ eidx,
                        int E) {
    __shared__ float sb[NB_MAX + 2];
    __shared__ int sm_m;
    int t = threadIdx.x;
    if (t == 0) sm_m = g_m;
    if (t < NB_MAX + 2) sb[t] = g_bounds[t];
    __syncthreads();
    int e = blockIdx.x * 256 + t;
    if (e >= E) return;
    float a = eattr[e];
    int s, d;
    if (g_is64) {
        const long long* p = (const long long*)eidx;
        s = (int)p[e]; d = (int)p[E + e];
    } else {
        const int* p = (const int*)eidx;
        s = p[e]; d = p[E + e];
    }
    g_a[e] = a; g_src[e] = s; g_dst[e] = d;
    int m = sm_m, k = 0;
    for (int i = 1; i <= m; i++) k += (a > sb[i]) ? 1 : 0;
    g_bucket[e] = k;
    atomicAdd(&g_hist[k], 1);
}

// ---------------- k4: exclusive scan + zero cursors/stats + transpose root_w ----------------
__global__ void k4_scan(const float* __restrict__ root_w) {
    int t = threadIdx.x;   // 256
    if (t == 0) {
        int run = 0, m = g_m;
        for (int k = 0; k <= m; k++) { g_off[k] = run; run += g_hist[k]; }
        g_off[m + 1] = run;
    }
    for (int i = t; i < NB_MAX + 2; i += 256) g_cursor[i] = 0;
    if (t < H) { g_sum[t] = 0.f; g_sq[t] = 0.f; }
    for (int idx = t; idx < H * H; idx += 256) {
        int o = idx / H, i = idx % H;
        g_rwT[i * H + o] = root_w[idx];
    }
}

// ---------------- k5: scatter edges into bucket order ----------------
__global__ void k5_scatter(int E) {
    int e = blockIdx.x * 256 + threadIdx.x;
    if (e >= E) return;
    int k = g_bucket[e];
    int pos = atomicAdd(&g_cursor[k], 1);
    g_order[g_off[k] + pos] = e;
}

// ---------------- k6: root GEMM  g_agg = x @ root_w^T + conv_bias ----------------
#define RB 128
__global__ __launch_bounds__(RB) void k6_root(const float* __restrict__ x,
                                              const float* __restrict__ cbias, int N) {
    __shared__ float4 sW[H * 16];   // rwT [i][o4], 16 KB, broadcast reads
    __shared__ float4 sB[16];
    int t = threadIdx.x;
    const float4* gw = (const float4*)g_rwT;
    for (int i = t; i < H * 16; i += RB) sW[i] = gw[i];
    if (t < 16) sB[t] = ((const float4*)cbias)[t];
    __syncthreads();
    int v = blockIdx.x * RB + t;
    if (v >= N) return;
    const float4* xr = (const float4*)(x + (size_t)v * H);
    float4 acc[16];
#pragma unroll
    for (int o = 0; o < 16; o++) acc[o] = sB[o];
#pragma unroll 1
    for (int ig = 0; ig < 16; ig++) {
        float4 xq = __ldg(&xr[ig]);
#pragma unroll
        for (int c = 0; c < 4; c++) {
            float xi = (c == 0) ? xq.x : (c == 1) ? xq.y : (c == 2) ? xq.z : xq.w;
            const float4* wr = sW + (ig * 4 + c) * 16;
#pragma unroll
            for (int o = 0; o < 16; o++) {
                float4 w = wr[o];
                acc[o].x += xi * w.x; acc[o].y += xi * w.y;
                acc[o].z += xi * w.z; acc[o].w += xi * w.w;
            }
        }
    }
    float4* outr = (float4*)(g_agg + (size_t)v * H);
#pragma unroll
    for (int o = 0; o < 16; o++) outr[o] = acc[o];
}

// ---------------- k7: bucketed edge messages + scatter-add ----------------
#define EB 128
#define GX 128
__global__ __launch_bounds__(EB) void k7_edges(const float* __restrict__ x) {
    int k = blockIdx.y;
    if (k > g_m) return;
    int lo = g_off[k], hi = g_off[k + 1];
    int first = lo + blockIdx.x * EB;
    if (first >= hi) return;
    __shared__ float4 sP[H * 16], sQ[H * 16];   // 16 KB each
    int t = threadIdx.x;
    const float4* gP = (const float4*)(g_P + (size_t)k * H * H);
    const float4* gQ = (const float4*)(g_Q + (size_t)k * H * H);
    for (int i = t; i < H * 16; i += EB) { sP[i] = gP[i]; sQ[i] = gQ[i]; }
    __syncthreads();
    for (int s = first; s < hi; s += GX * EB) {
        int idx = s + t;
        if (idx >= hi) continue;
        int e = g_order[idx];
        float a = g_a[e];
        int src = g_src[e], dst = g_dst[e];
        const float4* xr = (const float4*)(x + (size_t)src * H);
        float4 acc[16];
#pragma unroll
        for (int o = 0; o < 16; o++) acc[o] = make_float4(0.f, 0.f, 0.f, 0.f);
#pragma unroll 1
        for (int ig = 0; ig < 16; ig++) {
            float4 xq = __ldg(&xr[ig]);
#pragma unroll
            for (int c = 0; c < 4; c++) {
                float xi = (c == 0) ? xq.x : (c == 1) ? xq.y : (c == 2) ? xq.z : xq.w;
                int i = ig * 4 + c;
                const float4* pr = sP + i * 16;
                const float4* qr = sQ + i * 16;
#pragma unroll
                for (int o = 0; o < 16; o++) {
                    float4 p = pr[o], q = qr[o];
                    acc[o].x += xi * fmaf(a, p.x, q.x);
                    acc[o].y += xi * fmaf(a, p.y, q.y);
                    acc[o].z += xi * fmaf(a, p.z, q.z);
                    acc[o].w += xi * fmaf(a, p.w, q.w);
                }
            }
        }
        float* outp = g_agg + (size_t)dst * H;
#pragma unroll
        for (int o = 0; o < 16; o++) {
            atomicAdd(outp + o * 4 + 0, acc[o].x);
            atomicAdd(outp + o * 4 + 1, acc[o].y);
            atomicAdd(outp + o * 4 + 2, acc[o].z);
            atomicAdd(outp + o * 4 + 3, acc[o].w);
        }
    }
}

// ---------------- k8: BN column stats ----------------
__global__ void k8_bnstats(int N) {
    int t = threadIdx.x;          // 256
    int c = t & 63;
    int r0 = blockIdx.x * 4 + (t >> 6);
    float s = 0.f, q = 0.f;
    for (int r = r0; r < N; r += gridDim.x * 4) {
        float v = g_agg[r * H + c];
        s += v; q += v * v;
    }
    __shared__ float ss[256], sq[256];
    ss[t] = s; sq[t] = q;
    __syncthreads();
    if (t < 64) {
        s = ss[t] + ss[t + 64] + ss[t + 128] + ss[t + 192];
        q = sq[t] + sq[t + 64] + sq[t + 128] + sq[t + 192];
        atomicAdd(&g_sum[t], s);
        atomicAdd(&g_sq[t], q);
    }
}

// ---------------- k9: BN + ReLU + residual ----------------
__global__ void k9_final(const float* __restrict__ x, const float* __restrict__ gamma,
                         const float* __restrict__ beta, float* __restrict__ out, int N) {
    int idx = blockIdx.x * 256 + threadIdx.x;
    if (idx >= N * H) return;
    int c = idx & 63;
    float invN = 1.0f / (float)N;
    float mean = g_sum[c] * invN;
    float var  = g_sq[c] * invN - mean * mean;
    float v = g_agg[idx];
    float y = (v - mean) * rsqrtf(var + 1e-5f) * gamma[c] + beta[c];
    y = fmaxf(y, 0.f);
    out[idx] = x[idx] + y;
}

// ---------------- launch ----------------
extern "C" void kernel_launch(void* const* d_in, const int* in_sizes, int n_in,
                              void* d_out, int out_size) {
    const float* x      = (const float*)d_in[0];
    const float* eattr  = (const float*)d_in[1];
    const void*  eidx   = d_in[2];
    const float* w1     = (const float*)d_in[3];
    const float* b1     = (const float*)d_in[4];
    const float* w2     = (const float*)d_in[5];
    const float* b2     = (const float*)d_in[6];
    const float* root_w = (const float*)d_in[7];
    const float* cbias  = (const float*)d_in[8];
    const float* gamma  = (const float*)d_in[9];
    const float* beta   = (const float*)d_in[10];
    int N = in_sizes[0] / H;
    int E = in_sizes[1];

    k1_setup<<<1, 64>>>(w1, b1, eidx, E, N);
    k2_tables<<<NB_MAX, 256>>>(w1, b1, w2, b2);
    k3_prep<<<(E + 255) / 256, 256>>>(eattr, eidx, E);
    k4_scan<<<1, 256>>>(root_w);
    k5_scatter<<<(E + 255) / 256, 256>>>(E);
    k6_root<<<(N + RB - 1) / RB, RB>>>(x, cbias, N);
    k7_edges<<<dim3(GX, NB_MAX), EB>>>(x);
    k8_bnstats<<<160, 256>>>(N);
    k9_final<<<(N * H + 255) / 256, 256>>>(x, gamma, beta, (float*)d_out, N);
}

// round 2
// speedup vs baseline: 1.4339x; 1.4339x over previous
#include <cuda_runtime.h>

#define H 64
#define NB_MAX 66          // max intervals (<= 65) + slack
#define E_MAX 50048
#define N_MAX 20032

typedef unsigned long long ull;

// ---------------- f32x2 helpers ----------------
__device__ __forceinline__ ull pack2(float lo, float hi) {
    ull r; asm("mov.b64 %0,{%1,%2};" : "=l"(r) : "f"(lo), "f"(hi)); return r;
}
__device__ __forceinline__ float2 unpack2(ull v) {
    float2 f; asm("mov.b64 {%0,%1},%2;" : "=f"(f.x), "=f"(f.y) : "l"(v)); return f;
}
__device__ __forceinline__ ull fma2v(ull a, ull b, ull c) {
    ull d; asm("fma.rn.f32x2 %0,%1,%2,%3;" : "=l"(d) : "l"(a), "l"(b), "l"(c)); return d;
}

// ---------------- scratch (static device globals) ----------------
__device__ __align__(16) float g_P[NB_MAX * H * H];   // per-bucket P tables [k][i*64+o]
__device__ __align__(16) float g_Q[NB_MAX * H * H];   // per-bucket Q tables
__device__ float g_bounds[NB_MAX + 2];
__device__ int   g_cidx[NB_MAX + 2];                  // threshold feature index crossed entering bucket k
__device__ float g_csign[NB_MAX + 2];                 // +1 activate / -1 deactivate
__device__ int   g_m;                                 // interior thresholds; intervals = m+1
__device__ int   g_is64;
__device__ int4  g_tmp[E_MAX];                        // (src,dst,a_bits,bucket)
__device__ int   g_pos[E_MAX];
__device__ int4  g_es[E_MAX];                         // bucket-sorted (src,dst,a_bits,0)
__device__ int   g_hist[NB_MAX + 2];
__device__ __align__(16) float g_agg[N_MAX * H];
__device__ float g_sum[H], g_sq[H];

// ---------------- k1: thresholds+sort+signs, dtype detect, zero scratch ----------------
__global__ void k1_setup(const float* __restrict__ w1, const float* __restrict__ b1,
                         const void* __restrict__ eidx, int E, int N) {
    __shared__ float cand[H];
    __shared__ int   valid[H];
    __shared__ int   bad;
    int t = threadIdx.x;   // 64 threads
    if (t == 0) bad = 0;
    float w = w1[t], b = b1[t];
    float th = 0.f; int v = 0;
    if (w != 0.f) {
        th = -b / w;
        if (th > 0.f && th < 1.f) v = 1;
    }
    cand[t] = th; valid[t] = v;
    __syncthreads();
    // int64-vs-int32 autodetect
    const long long* p64 = (const long long*)eidx;
    for (int s = t; s < 512; s += 64) {
        long long vl = p64[s];
        if (vl < 0 || vl >= (long long)N) bad = 1;
    }
    __syncthreads();
    if (t == 0) {
        g_is64 = (bad == 0) ? 1 : 0;
        float arr[H]; int idxs[H];
        int m = 0;
        for (int j = 0; j < H; j++) if (valid[j]) { arr[m] = cand[j]; idxs[m] = j; m++; }
        for (int i = 1; i < m; i++) {          // insertion sort with index carry
            float xv = arr[i]; int xi = idxs[i]; int j = i - 1;
            while (j >= 0 && arr[j] > xv) { arr[j + 1] = arr[j]; idxs[j + 1] = idxs[j]; j--; }
            arr[j + 1] = xv; idxs[j + 1] = xi;
        }
        g_bounds[0] = 0.f;
        for (int i = 0; i < m; i++) {
            g_bounds[i + 1] = arr[i];
            g_cidx[i + 1]   = idxs[i];
            g_csign[i + 1]  = (cand[idxs[i]] >= 0.f, (w1[idxs[i]] > 0.f)) ? ((w1[idxs[i]] > 0.f) ? 1.f : -1.f) : -1.f;
        }
        g_bounds[m + 1] = 1.0f;
        g_m = m;
    }
    for (int i = t; i < NB_MAX + 2; i += 64) g_hist[i] = 0;
    g_sum[t] = 0.f; g_sq[t] = 0.f;
}

// ---------------- k2: incremental P_k / Q_k tables (rank-1 updates) ----------------
__global__ void k2_tables(const float* __restrict__ w1, const float* __restrict__ b1,
                          const float* __restrict__ w2, const float* __restrict__ b2) {
    __shared__ float sw[H], sb_[H];
    __shared__ float sbound[2];
    __shared__ int   scid[NB_MAX + 2];
    __shared__ float ssgn[NB_MAX + 2];
    __shared__ int   sm;
    int t = threadIdx.x;   // 256
    if (t < H) { sw[t] = w1[t]; sb_[t] = b1[t]; }
    if (t == 0) { sm = g_m; sbound[0] = g_bounds[0]; sbound[1] = g_bounds[1]; }
    if (t < NB_MAX + 2) { scid[t] = g_cidx[t]; ssgn[t] = g_csign[t]; }
    __syncthreads();
    int f = blockIdx.x * 256 + t;   // 16 blocks -> 4096
    float amid = 0.5f * (sbound[0] + sbound[1]);
    const float4* w2v = (const float4*)(w2 + (size_t)f * H);
    float p = 0.f, q = 0.f;
#pragma unroll
    for (int j4 = 0; j4 < 16; j4++) {
        float4 wv = w2v[j4];
#pragma unroll
        for (int c = 0; c < 4; c++) {
            int j = j4 * 4 + c;
            float el = (c == 0) ? wv.x : (c == 1) ? wv.y : (c == 2) ? wv.z : wv.w;
            float mask = (fmaf(amid, sw[j], sb_[j]) > 0.f) ? 1.f : 0.f;
            p = fmaf(mask * sw[j], el, p);
            q = fmaf(mask * sb_[j], el, q);
        }
    }
    float bb = b2[f];
    g_P[f] = p; g_Q[f] = q + bb;
    int m = sm;
    for (int k = 1; k <= m; k++) {
        int j = scid[k]; float s = ssgn[k];
        float el = __ldg(&w2[(size_t)f * H + j]);   // L1-resident after phase 0
        p = fmaf(s * sw[j], el, p);
        q = fmaf(s * sb_[j], el, q);
        g_P[k * (H * H) + f] = p;
        g_Q[k * (H * H) + f] = q + bb;
    }
}

// ---------------- k3: decode + bucket + histogram position ----------------
__global__ void k3_prep(const float* __restrict__ eattr, const void* __restrict__ eidx,
                        int E) {
    __shared__ float sbnd[NB_MAX + 2];
    __shared__ int sm_m;
    int t = threadIdx.x;
    if (t == 0) sm_m = g_m;
    if (t < NB_MAX + 2) sbnd[t] = g_bounds[t];
    __syncthreads();
    int e = blockIdx.x * 256 + t;
    if (e >= E) return;
    float a = eattr[e];
    int s, d;
    if (g_is64) {
        const long long* p = (const long long*)eidx;
        s = (int)p[e]; d = (int)p[E + e];
    } else {
        const int* p = (const int*)eidx;
        s = p[e]; d = p[E + e];
    }
    int m = sm_m, k = 0;
    for (int i = 1; i <= m; i++) k += (a > sbnd[i]) ? 1 : 0;
    int pos = atomicAdd(&g_hist[k], 1);
    g_tmp[e] = make_int4(s, d, __float_as_int(a), k);
    g_pos[e] = pos;
}

// ---------------- k5: scatter into bucket order (per-block scan) ----------------
__global__ void k5_scatter(int E) {
    __shared__ int soff[NB_MAX + 1];
    int t = threadIdx.x;
    if (t == 0) {
        int run = 0, m = g_m;
        for (int k = 0; k <= m; k++) { soff[k] = run; run += g_hist[k]; }
    }
    __syncthreads();
    int e = blockIdx.x * 256 + t;
    if (e >= E) return;
    int4 v = g_tmp[e];
    int idx = soff[v.w] + g_pos[e];
    v.w = 0;
    g_es[idx] = v;
}

// ---------------- k6: root GEMM  g_agg = x @ root_w^T + conv_bias (f32x2 dots) ----------------
#define RB 256
__global__ __launch_bounds__(RB) void k6_root(const float* __restrict__ x,
                                              const float* __restrict__ root_w,
                                              const float* __restrict__ cbias, int N) {
    __shared__ __align__(16) ull sW[H * 32];   // rw[o][i] as 32 packed pairs per row, 16 KB
    __shared__ float sB[H];
    int t = threadIdx.x;
    const int4* gw = (const int4*)root_w;
    int4* sWi = (int4*)sW;
    for (int i = t; i < H * 16; i += RB) sWi[i] = gw[i];
    if (t < H) sB[t] = cbias[t];
    __syncthreads();
    int v = blockIdx.x * RB + t;
    if (v >= N) return;
    const float4* xr = (const float4*)(x + (size_t)v * H);
    ull xp[32];
#pragma unroll
    for (int ig = 0; ig < 16; ig++) {
        float4 xq = __ldg(&xr[ig]);
        xp[ig * 2]     = pack2(xq.x, xq.y);
        xp[ig * 2 + 1] = pack2(xq.z, xq.w);
    }
    float4* outr = (float4*)(g_agg + (size_t)v * H);
#pragma unroll 1
    for (int o4 = 0; o4 < 16; o4++) {
        float res[4];
#pragma unroll
        for (int oo = 0; oo < 4; oo++) {
            int o = o4 * 4 + oo;
            const ulonglong2* wr = (const ulonglong2*)(sW + o * 32);
            ull acc = 0ull;
#pragma unroll
            for (int i2 = 0; i2 < 16; i2++) {
                ulonglong2 wv = wr[i2];
                acc = fma2v(xp[i2 * 2],     wv.x, acc);
                acc = fma2v(xp[i2 * 2 + 1], wv.y, acc);
            }
            float2 h = unpack2(acc);
            res[oo] = h.x + h.y + sB[o];
        }
        outr[o4] = make_float4(res[0], res[1], res[2], res[3]);
    }
}

// ---------------- k7: bucketed edge messages + vector scatter-add ----------------
#define EB 128
#define GX 128
__global__ __launch_bounds__(EB) void k7_edges(const float* __restrict__ x) {
    int k = blockIdx.y;
    if (k > g_m) return;
    __shared__ int srange[2];
    int t = threadIdx.x;
    if (t == 0) {
        int run = 0;
        for (int i = 0; i < k; i++) run += g_hist[i];
        srange[0] = run; srange[1] = run + g_hist[k];
    }
    __syncthreads();
    int lo = srange[0], hi = srange[1];
    int first = lo + blockIdx.x * EB;
    if (first >= hi) return;
    __shared__ __align__(16) ull sP[H * 32], sQ[H * 32];   // 16 KB each
    const int4* gP = (const int4*)(g_P + (size_t)k * H * H);
    const int4* gQ = (const int4*)(g_Q + (size_t)k * H * H);
    int4* sPi = (int4*)sP; int4* sQi = (int4*)sQ;
    for (int i = t; i < 1024; i += EB) { sPi[i] = gP[i]; sQi[i] = gQ[i]; }
    __syncthreads();
    for (int base = first; base < hi; base += GX * EB) {
        int idx = base + t;
        if (idx >= hi) continue;
        int4 ed = g_es[idx];
        float a = __int_as_float(ed.z);
        ull a2 = pack2(a, a);
        const float4* xr = (const float4*)(x + (size_t)ed.x * H);
        ull acc[32];
#pragma unroll
        for (int i = 0; i < 32; i++) acc[i] = 0ull;
#pragma unroll 1
        for (int ig = 0; ig < 16; ig++) {
            float4 xq = __ldg(&xr[ig]);
#pragma unroll
            for (int c = 0; c < 4; c++) {
                float xi = (c == 0) ? xq.x : (c == 1) ? xq.y : (c == 2) ? xq.z : xq.w;
                ull xi2 = pack2(xi, xi);
                int i = ig * 4 + c;
                const ulonglong2* pr = (const ulonglong2*)(sP + i * 32);
                const ulonglong2* qr = (const ulonglong2*)(sQ + i * 32);
#pragma unroll
                for (int o2 = 0; o2 < 16; o2++) {
                    ulonglong2 pv = pr[o2];
                    ulonglong2 qv = qr[o2];
                    ull t0 = fma2v(a2, pv.x, qv.x);
                    ull t1 = fma2v(a2, pv.y, qv.y);
                    acc[o2 * 2]     = fma2v(xi2, t0, acc[o2 * 2]);
                    acc[o2 * 2 + 1] = fma2v(xi2, t1, acc[o2 * 2 + 1]);
                }
            }
        }
        float4* outp = (float4*)(g_agg + (size_t)ed.y * H);
#pragma unroll
        for (int o = 0; o < 16; o++) {
            float2 l  = unpack2(acc[o * 2]);
            float2 hh = unpack2(acc[o * 2 + 1]);
            atomicAdd(&outp[o], make_float4(l.x, l.y, hh.x, hh.y));
        }
    }
}

// ---------------- k8: BN column stats ----------------
__global__ void k8_bnstats(int N) {
    int t = threadIdx.x;          // 256
    int c = t & 63;
    int r0 = blockIdx.x * 4 + (t >> 6);
    float s = 0.f, q = 0.f;
    for (int r = r0; r < N; r += gridDim.x * 4) {
        float v = g_agg[r * H + c];
        s += v; q += v * v;
    }
    __shared__ float ss[256], sq[256];
    ss[t] = s; sq[t] = q;
    __syncthreads();
    if (t < 64) {
        s = ss[t] + ss[t + 64] + ss[t + 128] + ss[t + 192];
        q = sq[t] + sq[t + 64] + sq[t + 128] + sq[t + 192];
        atomicAdd(&g_sum[t], s);
        atomicAdd(&g_sq[t], q);
    }
}

// ---------------- k9: BN + ReLU + residual (vectorized) ----------------
__global__ void k9_final(const float* __restrict__ x, const float* __restrict__ gamma,
                         const float* __restrict__ beta, float* __restrict__ out, int N) {
    int v = blockIdx.x * 256 + threadIdx.x;
    int total = N * 16;
    if (v >= total) return;
    int c4 = (v & 15) * 4;
    float invN = 1.0f / (float)N;
    float4 g  = ((const float4*)g_agg)[v];
    float4 xv = ((const float4*)x)[v];
    float4 r;
#define BN1(comp, cc) { \
        float mean = g_sum[cc] * invN; \
        float var  = g_sq[cc] * invN - mean * mean; \
        float y = (g.comp - mean) * rsqrtf(var + 1e-5f) * gamma[cc] + beta[cc]; \
        y = fmaxf(y, 0.f); \
        r.comp = xv.comp + y; }
    BN1(x, c4) BN1(y, c4 + 1) BN1(z, c4 + 2) BN1(w, c4 + 3)
#undef BN1
    ((float4*)out)[v] = r;
}

// ---------------- launch ----------------
extern "C" void kernel_launch(void* const* d_in, const int* in_sizes, int n_in,
                              void* d_out, int out_size) {
    const float* x      = (const float*)d_in[0];
    const float* eattr  = (const float*)d_in[1];
    const void*  eidx   = d_in[2];
    const float* w1     = (const float*)d_in[3];
    const float* b1     = (const float*)d_in[4];
    const float* w2     = (const float*)d_in[5];
    const float* b2     = (const float*)d_in[6];
    const float* root_w = (const float*)d_in[7];
    const float* cbias  = (const float*)d_in[8];
    const float* gamma  = (const float*)d_in[9];
    const float* beta   = (const float*)d_in[10];
    int N = in_sizes[0] / H;
    int E = in_sizes[1];

    k1_setup<<<1, 64>>>(w1, b1, eidx, E, N);
    k2_tables<<<16, 256>>>(w1, b1, w2, b2);
    k3_prep<<<(E + 255) / 256, 256>>>(eattr, eidx, E);
    k5_scatter<<<(E + 255) / 256, 256>>>(E);
    k6_root<<<(N + RB - 1) / RB, RB>>>(x, root_w, cbias, N);
    k7_edges<<<dim3(GX, NB_MAX), EB>>>(x);
    k8_bnstats<<<160, 256>>>(N);
    k9_final<<<(N * 16 + 255) / 256, 256>>>(x, gamma, beta, (float*)d_out, N);
}

// round 3
// speedup vs baseline: 1.4361x; 1.0015x over previous
#include <cuda_runtime.h>

#define H 64
#define NB_MAX 66          // max intervals (<= 65) + slack
#define E_MAX 50048
#define N_MAX 20032

typedef unsigned long long ull;

// ---------------- f32x2 helpers ----------------
__device__ __forceinline__ ull pack2(float lo, float hi) {
    ull r; asm("mov.b64 %0,{%1,%2};" : "=l"(r) : "f"(lo), "f"(hi)); return r;
}
__device__ __forceinline__ float2 unpack2(ull v) {
    float2 f; asm("mov.b64 {%0,%1},%2;" : "=f"(f.x), "=f"(f.y) : "l"(v)); return f;
}
__device__ __forceinline__ ull fma2v(ull a, ull b, ull c) {
    ull d; asm("fma.rn.f32x2 %0,%1,%2,%3;" : "=l"(d) : "l"(a), "l"(b), "l"(c)); return d;
}

// ---------------- scratch (static device globals) ----------------
__device__ __align__(16) float g_P[NB_MAX * H * H];   // per-bucket P tables [k][i*64+o]
__device__ __align__(16) float g_Q[NB_MAX * H * H];   // per-bucket Q tables
__device__ float g_bounds[NB_MAX + 2];
__device__ int   g_cidx[NB_MAX + 2];                  // threshold feature index crossed entering bucket k
__device__ float g_csign[NB_MAX + 2];                 // +1 activate / -1 deactivate
__device__ int   g_m;                                 // interior thresholds; intervals = m+1
__device__ int   g_is64;
__device__ int4  g_tmp[E_MAX];                        // (src,dst,a_bits,bucket)
__device__ int   g_pos[E_MAX];
__device__ int4  g_es[E_MAX];                         // bucket-sorted (src,dst,a_bits,0)
__device__ int   g_hist[NB_MAX + 2];
__device__ __align__(16) float g_agg[N_MAX * H];
__device__ float g_sum[H], g_sq[H];

// ---------------- k1: thresholds+sort+signs, dtype detect, zero scratch ----------------
__global__ void k1_setup(const float* __restrict__ w1, const float* __restrict__ b1,
                         const void* __restrict__ eidx, int E, int N) {
    __shared__ float cand[H];
    __shared__ int   valid[H];
    __shared__ int   bad;
    int t = threadIdx.x;   // 64 threads
    if (t == 0) bad = 0;
    float w = w1[t], b = b1[t];
    float th = 0.f; int v = 0;
    if (w != 0.f) {
        th = -b / w;
        if (th > 0.f && th < 1.f) v = 1;
    }
    cand[t] = th; valid[t] = v;
    __syncthreads();
    // int64-vs-int32 autodetect
    const long long* p64 = (const long long*)eidx;
    for (int s = t; s < 512; s += 64) {
        long long vl = p64[s];
        if (vl < 0 || vl >= (long long)N) bad = 1;
    }
    __syncthreads();
    if (t == 0) {
        g_is64 = (bad == 0) ? 1 : 0;
        float arr[H]; int idxs[H];
        int m = 0;
        for (int j = 0; j < H; j++) if (valid[j]) { arr[m] = cand[j]; idxs[m] = j; m++; }
        for (int i = 1; i < m; i++) {          // insertion sort with index carry
            float xv = arr[i]; int xi = idxs[i]; int j = i - 1;
            while (j >= 0 && arr[j] > xv) { arr[j + 1] = arr[j]; idxs[j + 1] = idxs[j]; j--; }
            arr[j + 1] = xv; idxs[j + 1] = xi;
        }
        g_bounds[0] = 0.f;
        for (int i = 0; i < m; i++) {
            g_bounds[i + 1] = arr[i];
            g_cidx[i + 1]   = idxs[i];
            g_csign[i + 1]  = (cand[idxs[i]] >= 0.f, (w1[idxs[i]] > 0.f)) ? ((w1[idxs[i]] > 0.f) ? 1.f : -1.f) : -1.f;
        }
        g_bounds[m + 1] = 1.0f;
        g_m = m;
    }
    for (int i = t; i < NB_MAX + 2; i += 64) g_hist[i] = 0;
    g_sum[t] = 0.f; g_sq[t] = 0.f;
}

// ---------------- k2: incremental P_k / Q_k tables (rank-1 updates) ----------------
__global__ void k2_tables(const float* __restrict__ w1, const float* __restrict__ b1,
                          const float* __restrict__ w2, const float* __restrict__ b2) {
    __shared__ float sw[H], sb_[H];
    __shared__ float sbound[2];
    __shared__ int   scid[NB_MAX + 2];
    __shared__ float ssgn[NB_MAX + 2];
    __shared__ int   sm;
    int t = threadIdx.x;   // 256
    if (t < H) { sw[t] = w1[t]; sb_[t] = b1[t]; }
    if (t == 0) { sm = g_m; sbound[0] = g_bounds[0]; sbound[1] = g_bounds[1]; }
    if (t < NB_MAX + 2) { scid[t] = g_cidx[t]; ssgn[t] = g_csign[t]; }
    __syncthreads();
    int f = blockIdx.x * 256 + t;   // 16 blocks -> 4096
    float amid = 0.5f * (sbound[0] + sbound[1]);
    const float4* w2v = (const float4*)(w2 + (size_t)f * H);
    float p = 0.f, q = 0.f;
#pragma unroll
    for (int j4 = 0; j4 < 16; j4++) {
        float4 wv = w2v[j4];
#pragma unroll
        for (int c = 0; c < 4; c++) {
            int j = j4 * 4 + c;
            float el = (c == 0) ? wv.x : (c == 1) ? wv.y : (c == 2) ? wv.z : wv.w;
            float mask = (fmaf(amid, sw[j], sb_[j]) > 0.f) ? 1.f : 0.f;
            p = fmaf(mask * sw[j], el, p);
            q = fmaf(mask * sb_[j], el, q);
        }
    }
    float bb = b2[f];
    g_P[f] = p; g_Q[f] = q + bb;
    int m = sm;
    for (int k = 1; k <= m; k++) {
        int j = scid[k]; float s = ssgn[k];
        float el = __ldg(&w2[(size_t)f * H + j]);   // L1-resident after phase 0
        p = fmaf(s * sw[j], el, p);
        q = fmaf(s * sb_[j], el, q);
        g_P[k * (H * H) + f] = p;
        g_Q[k * (H * H) + f] = q + bb;
    }
}

// ---------------- k3: decode + bucket + histogram position ----------------
__global__ void k3_prep(const float* __restrict__ eattr, const void* __restrict__ eidx,
                        int E) {
    __shared__ float sbnd[NB_MAX + 2];
    __shared__ int sm_m;
    int t = threadIdx.x;
    if (t == 0) sm_m = g_m;
    if (t < NB_MAX + 2) sbnd[t] = g_bounds[t];
    __syncthreads();
    int e = blockIdx.x * 256 + t;
    if (e >= E) return;
    float a = eattr[e];
    int s, d;
    if (g_is64) {
        const long long* p = (const long long*)eidx;
        s = (int)p[e]; d = (int)p[E + e];
    } else {
        const int* p = (const int*)eidx;
        s = p[e]; d = p[E + e];
    }
    int m = sm_m, k = 0;
    for (int i = 1; i <= m; i++) k += (a > sbnd[i]) ? 1 : 0;
    int pos = atomicAdd(&g_hist[k], 1);
    g_tmp[e] = make_int4(s, d, __float_as_int(a), k);
    g_pos[e] = pos;
}

// ---------------- k5: scatter into bucket order (per-block scan) ----------------
__global__ void k5_scatter(int E) {
    __shared__ int soff[NB_MAX + 1];
    int t = threadIdx.x;
    if (t == 0) {
        int run = 0, m = g_m;
        for (int k = 0; k <= m; k++) { soff[k] = run; run += g_hist[k]; }
    }
    __syncthreads();
    int e = blockIdx.x * 256 + t;
    if (e >= E) return;
    int4 v = g_tmp[e];
    int idx = soff[v.w] + g_pos[e];
    v.w = 0;
    g_es[idx] = v;
}

// ---------------- k6: root GEMM  g_agg = x @ root_w^T + conv_bias (f32x2 dots) ----------------
#define RB 256
__global__ __launch_bounds__(RB) void k6_root(const float* __restrict__ x,
                                              const float* __restrict__ root_w,
                                              const float* __restrict__ cbias, int N) {
    __shared__ __align__(16) ull sW[H * 32];   // rw[o][i] as 32 packed pairs per row, 16 KB
    __shared__ float sB[H];
    int t = threadIdx.x;
    const int4* gw = (const int4*)root_w;
    int4* sWi = (int4*)sW;
    for (int i = t; i < H * 16; i += RB) sWi[i] = gw[i];
    if (t < H) sB[t] = cbias[t];
    __syncthreads();
    int v = blockIdx.x * RB + t;
    if (v >= N) return;
    const float4* xr = (const float4*)(x + (size_t)v * H);
    ull xp[32];
#pragma unroll
    for (int ig = 0; ig < 16; ig++) {
        float4 xq = __ldg(&xr[ig]);
        xp[ig * 2]     = pack2(xq.x, xq.y);
        xp[ig * 2 + 1] = pack2(xq.z, xq.w);
    }
    float4* outr = (float4*)(g_agg + (size_t)v * H);
#pragma unroll 1
    for (int o4 = 0; o4 < 16; o4++) {
        float res[4];
#pragma unroll
        for (int oo = 0; oo < 4; oo++) {
            int o = o4 * 4 + oo;
            const ulonglong2* wr = (const ulonglong2*)(sW + o * 32);
            ull acc = 0ull;
#pragma unroll
            for (int i2 = 0; i2 < 16; i2++) {
                ulonglong2 wv = wr[i2];
                acc = fma2v(xp[i2 * 2],     wv.x, acc);
                acc = fma2v(xp[i2 * 2 + 1], wv.y, acc);
            }
            float2 h = unpack2(acc);
            res[oo] = h.x + h.y + sB[o];
        }
        outr[o4] = make_float4(res[0], res[1], res[2], res[3]);
    }
}

// ---------------- k7: bucketed edge messages + vector scatter-add ----------------
#define EB 128
#define GX 128
__global__ __launch_bounds__(EB) void k7_edges(const float* __restrict__ x) {
    int k = blockIdx.y;
    if (k > g_m) return;
    __shared__ int srange[2];
    int t = threadIdx.x;
    if (t == 0) {
        int run = 0;
        for (int i = 0; i < k; i++) run += g_hist[i];
        srange[0] = run; srange[1] = run + g_hist[k];
    }
    __syncthreads();
    int lo = srange[0], hi = srange[1];
    int first = lo + blockIdx.x * EB;
    if (first >= hi) return;
    __shared__ __align__(16) ull sP[H * 32], sQ[H * 32];   // 16 KB each
    const int4* gP = (const int4*)(g_P + (size_t)k * H * H);
    const int4* gQ = (const int4*)(g_Q + (size_t)k * H * H);
    int4* sPi = (int4*)sP; int4* sQi = (int4*)sQ;
    for (int i = t; i < 1024; i += EB) { sPi[i] = gP[i]; sQi[i] = gQ[i]; }
    __syncthreads();
    for (int base = first; base < hi; base += GX * EB) {
        int idx = base + t;
        if (idx >= hi) continue;
        int4 ed = g_es[idx];
        float a = __int_as_float(ed.z);
        ull a2 = pack2(a, a);
        const float4* xr = (const float4*)(x + (size_t)ed.x * H);
        ull acc[32];
#pragma unroll
        for (int i = 0; i < 32; i++) acc[i] = 0ull;
#pragma unroll 1
        for (int ig = 0; ig < 16; ig++) {
            float4 xq = __ldg(&xr[ig]);
#pragma unroll
            for (int c = 0; c < 4; c++) {
                float xi = (c == 0) ? xq.x : (c == 1) ? xq.y : (c == 2) ? xq.z : xq.w;
                ull xi2 = pack2(xi, xi);
                int i = ig * 4 + c;
                const ulonglong2* pr = (const ulonglong2*)(sP + i * 32);
                const ulonglong2* qr = (const ulonglong2*)(sQ + i * 32);
#pragma unroll
                for (int o2 = 0; o2 < 16; o2++) {
                    ulonglong2 pv = pr[o2];
                    ulonglong2 qv = qr[o2];
                    ull t0 = fma2v(a2, pv.x, qv.x);
                    ull t1 = fma2v(a2, pv.y, qv.y);
                    acc[o2 * 2]     = fma2v(xi2, t0, acc[o2 * 2]);
                    acc[o2 * 2 + 1] = fma2v(xi2, t1, acc[o2 * 2 + 1]);
                }
            }
        }
        float4* outp = (float4*)(g_agg + (size_t)ed.y * H);
#pragma unroll
        for (int o = 0; o < 16; o++) {
            float2 l  = unpack2(acc[o * 2]);
            float2 hh = unpack2(acc[o * 2 + 1]);
            atomicAdd(&outp[o], make_float4(l.x, l.y, hh.x, hh.y));
        }
    }
}

// ---------------- k8: BN column stats ----------------
__global__ void k8_bnstats(int N) {
    int t = threadIdx.x;          // 256
    int c = t & 63;
    int r0 = blockIdx.x * 4 + (t >> 6);
    float s = 0.f, q = 0.f;
    for (int r = r0; r < N; r += gridDim.x * 4) {
        float v = g_agg[r * H + c];
        s += v; q += v * v;
    }
    __shared__ float ss[256], sq[256];
    ss[t] = s; sq[t] = q;
    __syncthreads();
    if (t < 64) {
        s = ss[t] + ss[t + 64] + ss[t + 128] + ss[t + 192];
        q = sq[t] + sq[t + 64] + sq[t + 128] + sq[t + 192];
        atomicAdd(&g_sum[t], s);
        atomicAdd(&g_sq[t], q);
    }
}

// ---------------- k9: BN + ReLU + residual (vectorized) ----------------
__global__ void k9_final(const float* __restrict__ x, const float* __restrict__ gamma,
                         const float* __restrict__ beta, float* __restrict__ out, int N) {
    int v = blockIdx.x * 256 + threadIdx.x;
    int total = N * 16;
    if (v >= total) return;
    int c4 = (v & 15) * 4;
    float invN = 1.0f / (float)N;
    float4 g  = ((const float4*)g_agg)[v];
    float4 xv = ((const float4*)x)[v];
    float4 r;
#define BN1(comp, cc) { \
        float mean = g_sum[cc] * invN; \
        float var  = g_sq[cc] * invN - mean * mean; \
        float y = (g.comp - mean) * rsqrtf(var + 1e-5f) * gamma[cc] + beta[cc]; \
        y = fmaxf(y, 0.f); \
        r.comp = xv.comp + y; }
    BN1(x, c4) BN1(y, c4 + 1) BN1(z, c4 + 2) BN1(w, c4 + 3)
#undef BN1
    ((float4*)out)[v] = r;
}

// ---------------- launch ----------------
extern "C" void kernel_launch(void* const* d_in, const int* in_sizes, int n_in,
                              void* d_out, int out_size) {
    const float* x      = (const float*)d_in[0];
    const float* eattr  = (const float*)d_in[1];
    const void*  eidx   = d_in[2];
    const float* w1     = (const float*)d_in[3];
    const float* b1     = (const float*)d_in[4];
    const float* w2     = (const float*)d_in[5];
    const float* b2     = (const float*)d_in[6];
    const float* root_w = (const float*)d_in[7];
    const float* cbias  = (const float*)d_in[8];
    const float* gamma  = (const float*)d_in[9];
    const float* beta   = (const float*)d_in[10];
    int N = in_sizes[0] / H;
    int E = in_sizes[1];

    k1_setup<<<1, 64>>>(w1, b1, eidx, E, N);
    k2_tables<<<16, 256>>>(w1, b1, w2, b2);
    k3_prep<<<(E + 255) / 256, 256>>>(eattr, eidx, E);
    k5_scatter<<<(E + 255) / 256, 256>>>(E);
    k6_root<<<(N + RB - 1) / RB, RB>>>(x, root_w, cbias, N);
    k7_edges<<<dim3(GX, NB_MAX), EB>>>(x);
    k8_bnstats<<<160, 256>>>(N);
    k9_final<<<(N * 16 + 255) / 256, 256>>>(x, gamma, beta, (float*)d_out, N);
}

// round 4
// speedup vs baseline: 1.4391x; 1.0021x over previous
#include <cuda_runtime.h>

#define H 64
#define NB_MAX 66          // max intervals (<= 65) + slack
#define E_MAX 50048
#define N_MAX 20032

typedef unsigned long long ull;

// ---------------- f32x2 helpers ----------------
__device__ __forceinline__ ull pack2(float lo, float hi) {
    ull r; asm("mov.b64 %0,{%1,%2};" : "=l"(r) : "f"(lo), "f"(hi)); return r;
}
__device__ __forceinline__ float2 unpack2(ull v) {
    float2 f; asm("mov.b64 {%0,%1},%2;" : "=f"(f.x), "=f"(f.y) : "l"(v)); return f;
}
__device__ __forceinline__ ull fma2v(ull a, ull b, ull c) {
    ull d; asm("fma.rn.f32x2 %0,%1,%2,%3;" : "=l"(d) : "l"(a), "l"(b), "l"(c)); return d;
}

// ---------------- scratch (static device globals) ----------------
__device__ __align__(16) float g_P[NB_MAX * H * H];   // per-bucket P tables [k][i*64+o]
__device__ __align__(16) float g_Q[NB_MAX * H * H];   // per-bucket Q tables
__device__ float g_bounds[NB_MAX + 2];
__device__ int   g_cidx[NB_MAX + 2];                  // threshold feature index crossed entering bucket k
__device__ float g_csign[NB_MAX + 2];                 // +1 activate / -1 deactivate
__device__ int   g_m;                                 // interior thresholds; intervals = m+1
__device__ int   g_is64;
__device__ int4  g_tmp[E_MAX];                        // (src,dst,a_bits,bucket)
__device__ int   g_pos[E_MAX];
__device__ int4  g_es[E_MAX];                         // bucket-sorted (src,dst,a_bits,0)
__device__ int   g_hist[NB_MAX + 2];
__device__ __align__(16) float g_agg[N_MAX * H];
__device__ float g_sum[H], g_sq[H];

// ---------------- k1: thresholds+sort+signs, dtype detect, zero scratch ----------------
__global__ void k1_setup(const float* __restrict__ w1, const float* __restrict__ b1,
                         const void* __restrict__ eidx, int E, int N) {
    __shared__ float cand[H];
    __shared__ int   valid[H];
    __shared__ int   bad;
    int t = threadIdx.x;   // 64 threads
    if (t == 0) bad = 0;
    float w = w1[t], b = b1[t];
    float th = 0.f; int v = 0;
    if (w != 0.f) {
        th = -b / w;
        if (th > 0.f && th < 1.f) v = 1;
    }
    cand[t] = th; valid[t] = v;
    __syncthreads();
    // int64-vs-int32 autodetect
    const long long* p64 = (const long long*)eidx;
    for (int s = t; s < 512; s += 64) {
        long long vl = p64[s];
        if (vl < 0 || vl >= (long long)N) bad = 1;
    }
    __syncthreads();
    if (t == 0) {
        g_is64 = (bad == 0) ? 1 : 0;
        float arr[H]; int idxs[H];
        int m = 0;
        for (int j = 0; j < H; j++) if (valid[j]) { arr[m] = cand[j]; idxs[m] = j; m++; }
        for (int i = 1; i < m; i++) {          // insertion sort with index carry
            float xv = arr[i]; int xi = idxs[i]; int j = i - 1;
            while (j >= 0 && arr[j] > xv) { arr[j + 1] = arr[j]; idxs[j + 1] = idxs[j]; j--; }
            arr[j + 1] = xv; idxs[j + 1] = xi;
        }
        g_bounds[0] = 0.f;
        for (int i = 0; i < m; i++) {
            g_bounds[i + 1] = arr[i];
            g_cidx[i + 1]   = idxs[i];
            g_csign[i + 1]  = (cand[idxs[i]] >= 0.f, (w1[idxs[i]] > 0.f)) ? ((w1[idxs[i]] > 0.f) ? 1.f : -1.f) : -1.f;
        }
        g_bounds[m + 1] = 1.0f;
        g_m = m;
    }
    for (int i = t; i < NB_MAX + 2; i += 64) g_hist[i] = 0;
    g_sum[t] = 0.f; g_sq[t] = 0.f;
}

// ---------------- k2: incremental P_k / Q_k tables (rank-1 updates) ----------------
__global__ void k2_tables(const float* __restrict__ w1, const float* __restrict__ b1,
                          const float* __restrict__ w2, const float* __restrict__ b2) {
    __shared__ float sw[H], sb_[H];
    __shared__ float sbound[2];
    __shared__ int   scid[NB_MAX + 2];
    __shared__ float ssgn[NB_MAX + 2];
    __shared__ int   sm;
    int t = threadIdx.x;   // 256
    if (t < H) { sw[t] = w1[t]; sb_[t] = b1[t]; }
    if (t == 0) { sm = g_m; sbound[0] = g_bounds[0]; sbound[1] = g_bounds[1]; }
    if (t < NB_MAX + 2) { scid[t] = g_cidx[t]; ssgn[t] = g_csign[t]; }
    __syncthreads();
    int f = blockIdx.x * 256 + t;   // 16 blocks -> 4096
    float amid = 0.5f * (sbound[0] + sbound[1]);
    const float4* w2v = (const float4*)(w2 + (size_t)f * H);
    float p = 0.f, q = 0.f;
#pragma unroll
    for (int j4 = 0; j4 < 16; j4++) {
        float4 wv = w2v[j4];
#pragma unroll
        for (int c = 0; c < 4; c++) {
            int j = j4 * 4 + c;
            float el = (c == 0) ? wv.x : (c == 1) ? wv.y : (c == 2) ? wv.z : wv.w;
            float mask = (fmaf(amid, sw[j], sb_[j]) > 0.f) ? 1.f : 0.f;
            p = fmaf(mask * sw[j], el, p);
            q = fmaf(mask * sb_[j], el, q);
        }
    }
    float bb = b2[f];
    g_P[f] = p; g_Q[f] = q + bb;
    int m = sm;
    for (int k = 1; k <= m; k++) {
        int j = scid[k]; float s = ssgn[k];
        float el = __ldg(&w2[(size_t)f * H + j]);   // L1-resident after phase 0
        p = fmaf(s * sw[j], el, p);
        q = fmaf(s * sb_[j], el, q);
        g_P[k * (H * H) + f] = p;
        g_Q[k * (H * H) + f] = q + bb;
    }
}

// ---------------- k3: decode + bucket + histogram position ----------------
__global__ void k3_prep(const float* __restrict__ eattr, const void* __restrict__ eidx,
                        int E) {
    __shared__ float sbnd[NB_MAX + 2];
    __shared__ int sm_m;
    int t = threadIdx.x;
    if (t == 0) sm_m = g_m;
    if (t < NB_MAX + 2) sbnd[t] = g_bounds[t];
    __syncthreads();
    int e = blockIdx.x * 256 + t;
    if (e >= E) return;
    float a = eattr[e];
    int s, d;
    if (g_is64) {
        const long long* p = (const long long*)eidx;
        s = (int)p[e]; d = (int)p[E + e];
    } else {
        const int* p = (const int*)eidx;
        s = p[e]; d = p[E + e];
    }
    int m = sm_m, k = 0;
    for (int i = 1; i <= m; i++) k += (a > sbnd[i]) ? 1 : 0;
    int pos = atomicAdd(&g_hist[k], 1);
    g_tmp[e] = make_int4(s, d, __float_as_int(a), k);
    g_pos[e] = pos;
}

// ---------------- k5: scatter into bucket order (per-block scan) ----------------
__global__ void k5_scatter(int E) {
    __shared__ int soff[NB_MAX + 1];
    int t = threadIdx.x;
    if (t == 0) {
        int run = 0, m = g_m;
        for (int k = 0; k <= m; k++) { soff[k] = run; run += g_hist[k]; }
    }
    __syncthreads();
    int e = blockIdx.x * 256 + t;
    if (e >= E) return;
    int4 v = g_tmp[e];
    int idx = soff[v.w] + g_pos[e];
    v.w = 0;
    g_es[idx] = v;
}

// ---------------- k6: root GEMM  g_agg = x @ root_w^T + conv_bias (f32x2 dots) ----------------
#define RB 256
__global__ __launch_bounds__(RB) void k6_root(const float* __restrict__ x,
                                              const float* __restrict__ root_w,
                                              const float* __restrict__ cbias, int N) {
    __shared__ __align__(16) ull sW[H * 32];   // rw[o][i] as 32 packed pairs per row, 16 KB
    __shared__ float sB[H];
    int t = threadIdx.x;
    const int4* gw = (const int4*)root_w;
    int4* sWi = (int4*)sW;
    for (int i = t; i < H * 16; i += RB) sWi[i] = gw[i];
    if (t < H) sB[t] = cbias[t];
    __syncthreads();
    int v = blockIdx.x * RB + t;
    if (v >= N) return;
    const float4* xr = (const float4*)(x + (size_t)v * H);
    ull xp[32];
#pragma unroll
    for (int ig = 0; ig < 16; ig++) {
        float4 xq = __ldg(&xr[ig]);
        xp[ig * 2]     = pack2(xq.x, xq.y);
        xp[ig * 2 + 1] = pack2(xq.z, xq.w);
    }
    float4* outr = (float4*)(g_agg + (size_t)v * H);
#pragma unroll 1
    for (int o4 = 0; o4 < 16; o4++) {
        float res[4];
#pragma unroll
        for (int oo = 0; oo < 4; oo++) {
            int o = o4 * 4 + oo;
            const ulonglong2* wr = (const ulonglong2*)(sW + o * 32);
            ull acc = 0ull;
#pragma unroll
            for (int i2 = 0; i2 < 16; i2++) {
                ulonglong2 wv = wr[i2];
                acc = fma2v(xp[i2 * 2],     wv.x, acc);
                acc = fma2v(xp[i2 * 2 + 1], wv.y, acc);
            }
            float2 h = unpack2(acc);
            res[oo] = h.x + h.y + sB[o];
        }
        outr[o4] = make_float4(res[0], res[1], res[2], res[3]);
    }
}

// ---------------- k7: bucketed edge messages + vector scatter-add ----------------
#define EB 128
#define GX 128
__global__ __launch_bounds__(EB) void k7_edges(const float* __restrict__ x) {
    int k = blockIdx.y;
    if (k > g_m) return;
    __shared__ int srange[2];
    int t = threadIdx.x;
    if (t == 0) {
        int run = 0;
        for (int i = 0; i < k; i++) run += g_hist[i];
        srange[0] = run; srange[1] = run + g_hist[k];
    }
    __syncthreads();
    int lo = srange[0], hi = srange[1];
    int first = lo + blockIdx.x * EB;
    if (first >= hi) return;
    __shared__ __align__(16) ull sP[H * 32], sQ[H * 32];   // 16 KB each
    const int4* gP = (const int4*)(g_P + (size_t)k * H * H);
    const int4* gQ = (const int4*)(g_Q + (size_t)k * H * H);
    int4* sPi = (int4*)sP; int4* sQi = (int4*)sQ;
    for (int i = t; i < 1024; i += EB) { sPi[i] = gP[i]; sQi[i] = gQ[i]; }
    __syncthreads();
    for (int base = first; base < hi; base += GX * EB) {
        int idx = base + t;
        if (idx >= hi) continue;
        int4 ed = g_es[idx];
        float a = __int_as_float(ed.z);
        ull a2 = pack2(a, a);
        const float4* xr = (const float4*)(x + (size_t)ed.x * H);
        ull acc[32];
#pragma unroll
        for (int i = 0; i < 32; i++) acc[i] = 0ull;
#pragma unroll 1
        for (int ig = 0; ig < 16; ig++) {
            float4 xq = __ldg(&xr[ig]);
#pragma unroll
            for (int c = 0; c < 4; c++) {
                float xi = (c == 0) ? xq.x : (c == 1) ? xq.y : (c == 2) ? xq.z : xq.w;
                ull xi2 = pack2(xi, xi);
                int i = ig * 4 + c;
                const ulonglong2* pr = (const ulonglong2*)(sP + i * 32);
                const ulonglong2* qr = (const ulonglong2*)(sQ + i * 32);
#pragma unroll
                for (int o2 = 0; o2 < 16; o2++) {
                    ulonglong2 pv = pr[o2];
                    ulonglong2 qv = qr[o2];
                    ull t0 = fma2v(a2, pv.x, qv.x);
                    ull t1 = fma2v(a2, pv.y, qv.y);
                    acc[o2 * 2]     = fma2v(xi2, t0, acc[o2 * 2]);
                    acc[o2 * 2 + 1] = fma2v(xi2, t1, acc[o2 * 2 + 1]);
                }
            }
        }
        float4* outp = (float4*)(g_agg + (size_t)ed.y * H);
#pragma unroll
        for (int o = 0; o < 16; o++) {
            float2 l  = unpack2(acc[o * 2]);
            float2 hh = unpack2(acc[o * 2 + 1]);
            atomicAdd(&outp[o], make_float4(l.x, l.y, hh.x, hh.y));
        }
    }
}

// ---------------- k8: BN column stats ----------------
__global__ void k8_bnstats(int N) {
    int t = threadIdx.x;          // 256
    int c = t & 63;
    int r0 = blockIdx.x * 4 + (t >> 6);
    float s = 0.f, q = 0.f;
    for (int r = r0; r < N; r += gridDim.x * 4) {
        float v = g_agg[r * H + c];
        s += v; q += v * v;
    }
    __shared__ float ss[256], sq[256];
    ss[t] = s; sq[t] = q;
    __syncthreads();
    if (t < 64) {
        s = ss[t] + ss[t + 64] + ss[t + 128] + ss[t + 192];
        q = sq[t] + sq[t + 64] + sq[t + 128] + sq[t + 192];
        atomicAdd(&g_sum[t], s);
        atomicAdd(&g_sq[t], q);
    }
}

// ---------------- k9: BN + ReLU + residual (vectorized) ----------------
__global__ void k9_final(const float* __restrict__ x, const float* __restrict__ gamma,
                         const float* __restrict__ beta, float* __restrict__ out, int N) {
    int v = blockIdx.x * 256 + threadIdx.x;
    int total = N * 16;
    if (v >= total) return;
    int c4 = (v & 15) * 4;
    float invN = 1.0f / (float)N;
    float4 g  = ((const float4*)g_agg)[v];
    float4 xv = ((const float4*)x)[v];
    float4 r;
#define BN1(comp, cc) { \
        float mean = g_sum[cc] * invN; \
        float var  = g_sq[cc] * invN - mean * mean; \
        float y = (g.comp - mean) * rsqrtf(var + 1e-5f) * gamma[cc] + beta[cc]; \
        y = fmaxf(y, 0.f); \
        r.comp = xv.comp + y; }
    BN1(x, c4) BN1(y, c4 + 1) BN1(z, c4 + 2) BN1(w, c4 + 3)
#undef BN1
    ((float4*)out)[v] = r;
}

// ---------------- launch ----------------
extern "C" void kernel_launch(void* const* d_in, const int* in_sizes, int n_in,
                              void* d_out, int out_size) {
    const float* x      = (const float*)d_in[0];
    const float* eattr  = (const float*)d_in[1];
    const void*  eidx   = d_in[2];
    const float* w1     = (const float*)d_in[3];
    const float* b1     = (const float*)d_in[4];
    const float* w2     = (const float*)d_in[5];
    const float* b2     = (const float*)d_in[6];
    const float* root_w = (const float*)d_in[7];
    const float* cbias  = (const float*)d_in[8];
    const float* gamma  = (const float*)d_in[9];
    const float* beta   = (const float*)d_in[10];
    int N = in_sizes[0] / H;
    int E = in_sizes[1];

    k1_setup<<<1, 64>>>(w1, b1, eidx, E, N);
    k2_tables<<<16, 256>>>(w1, b1, w2, b2);
    k3_prep<<<(E + 255) / 256, 256>>>(eattr, eidx, E);
    k5_scatter<<<(E + 255) / 256, 256>>>(E);
    k6_root<<<(N + RB - 1) / RB, RB>>>(x, root_w, cbias, N);
    k7_edges<<<dim3(GX, NB_MAX), EB>>>(x);
    k8_bnstats<<<160, 256>>>(N);
    k9_final<<<(N * 16 + 255) / 256, 256>>>(x, gamma, beta, (float*)d_out, N);
}